// round 10
// baseline (speedup 1.0000x reference)
#include <cuda_runtime.h>
#include <cstdint>

// ---------------------------------------------------------------------------
// SphericalExpansion, round 10 = R9 minus registers, plus adaptive occupancy.
//
// Strided ownership (verified R4/R8/R9): lane L owns segment floats
// {L, L+32, L+64, L+96}; all share lm = L&15 (lane's own Y); n = (L>>4)+2k
// -> 4 rb gathered via shfl.idx; 4 scalar REDs (one 128B wavefront each).
//
// Register diet vs R9 (64 regs, 4 blk/SM):
//  * Y = f1 * (C0 + C1*(P*Q) + C2*z^2), f1/P/Q in {1,x,y,z} selected via
//    predicates (y^2 removed with x2+y2+z2=1). Packed coeffs: 3 u64, not 12.
//  * 2-edge packs (float2/int2 loads) halve live duo state.
// Grid = nSM * occupancy (queried) -> exactly one wave, no forced reg cap,
// NO spill risk (R6/R7 lesson: forced launch_bounds caps spill in hot loop).
// ---------------------------------------------------------------------------

typedef unsigned long long u64;

// f1 selector: 0 = 1, 1 = x, 2 = y, 3 = z
__constant__ int cFS[16] = {0,2,3,1, 0,0,0,0, 0,2,1,2, 3,1,3,1};
// P,Q selectors for the U1 = P*Q term: 0 = x, 1 = y, 2 = z
__constant__ int cPQ[16][2] = {
    {0,0},{0,0},{0,0},{0,0},
    {0,1},{1,2},{0,0},{2,0},
    {0,0},{0,0},{1,2},{0,0},
    {0,0},{0,0},{0,0},{0,0},
};
// {C0, C1, C2}: Y = f1 * (C0 + C1*(P*Q) + C2*z2)
__constant__ float cC[16][3] = {
    { 0.28209479177387814f, 0.f,                 0.f},
    { 0.4886025119029199f,  0.f,                 0.f},
    { 0.4886025119029199f,  0.f,                 0.f},
    { 0.4886025119029199f,  0.f,                 0.f},
    { 0.f,                  1.0925484305920792f, 0.f},
    { 0.f,                  1.0925484305920792f, 0.f},
    {-0.31539156525252005f, 0.f,                 0.9461746957575602f},
    { 0.f,                  1.0925484305920792f, 0.f},
    {-0.5462742152960396f,  1.0925484305920792f, 0.5462742152960396f},
    {-0.5900435899266435f,  2.360174359706574f,  0.5900435899266435f},
    { 0.f,                  2.890611442640554f,  0.f},
    {-0.4570457994644658f,  0.f,                 2.285228997322329f},
    {-1.1195289977703462f,  0.f,                 1.865881662950577f},
    {-0.4570457994644658f,  0.f,                 2.285228997322329f},
    {-1.445305721320277f,   2.890611442640554f,  1.445305721320277f},
    {-1.7701307697799304f,  2.360174359706574f,  1.7701307697799304f},
};
__constant__ int cLM2L[16] = {0,1,1,1, 2,2,2,2, 2,3,3,3, 3,3,3,3};

#define K2E (-2.8853900817779268f)   // -2*log2(e)

// ---- packed f32x2 helpers ----
__device__ __forceinline__ u64 pk2(float lo, float hi) {
    u64 r; asm("mov.b64 %0, {%1, %2};" : "=l"(r) : "f"(lo), "f"(hi)); return r;
}
__device__ __forceinline__ void upk2(float& lo, float& hi, u64 v) {
    asm("mov.b64 {%0, %1}, %2;" : "=f"(lo), "=f"(hi) : "l"(v));
}
__device__ __forceinline__ u64 mul2(u64 a, u64 b) {
    u64 r; asm("mul.rn.f32x2 %0, %1, %2;" : "=l"(r) : "l"(a), "l"(b)); return r;
}
__device__ __forceinline__ u64 add2(u64 a, u64 b) {
    u64 r; asm("add.rn.f32x2 %0, %1, %2;" : "=l"(r) : "l"(a), "l"(b)); return r;
}
__device__ __forceinline__ u64 fma2(u64 a, u64 b, u64 c) {
    u64 r; asm("fma.rn.f32x2 %0, %1, %2, %3;" : "=l"(r) : "l"(a), "l"(b), "l"(c)); return r;
}
__device__ __forceinline__ float ex2(float a) {
    float r; asm("ex2.approx.f32 %0, %1;" : "=f"(r) : "f"(a)); return r;
}
__device__ __forceinline__ float cutoff(float r) {
    const float u = __saturatef(fmaf(r, 2.0f, -9.0f));
    return fmaf(cospif(u), 0.5f, 0.5f);
}
__device__ __forceinline__ void red_f32(float* p, float v) {
    asm volatile("red.global.add.f32 [%0], %1;" :: "l"(p), "f"(v) : "memory");
}

__global__ void __launch_bounds__(256) zero_out_kernel(float4* out, int n4) {
    int i = blockIdx.x * blockDim.x + threadIdx.x;
    int stride = gridDim.x * blockDim.x;
    float4 zv = make_float4(0.f, 0.f, 0.f, 0.f);
    for (; i < n4; i += stride) out[i] = zv;
}

__global__ void __launch_bounds__(256) sph_expand_kernel(
    const float* __restrict__ dist,
    const float* __restrict__ dirs,      // [J,3]
    const float* __restrict__ centers,   // [32]
    const int*   __restrict__ zspec,     // [N_ATOMS]
    const int*   __restrict__ idx_i,     // [J]
    const int*   __restrict__ idx_j,     // [J]
    float*       __restrict__ out,       // [N_ATOMS*4*8*16]
    int J)
{
    const int lane  = threadIdx.x & 31;
    const int warp  = (blockIdx.x * blockDim.x + threadIdx.x) >> 5;
    const int nwarp = (gridDim.x * blockDim.x) >> 5;

    const int lm = lane & 15;
    const int h  = lane >> 4;            // parity of owned n
    const int l  = cLM2L[lm];

    // per-lane constants
    const float cenf = centers[lane];
    const u64 NEGCEN = pk2(-cenf, -cenf);
    const u64 KK = pk2(K2E, K2E);
    const u64 C0 = pk2(cC[lm][0], cC[lm][0]);
    const u64 C1 = pk2(cC[lm][1], cC[lm][1]);
    const u64 C2 = pk2(cC[lm][2], cC[lm][2]);

    // selector predicates (live in predicate regs, not GPRs)
    const int fs = cFS[lm];
    const int pi = cPQ[lm][0], qi = cPQ[lm][1];
    const bool f_y = (fs == 2), f_z = (fs == 3), f_one = (fs == 0);
    const bool p_y = (pi == 1), p_z = (pi == 2);
    const bool q_y = (qi == 1), q_z = (qi == 2);

    // rb shuffle sources: rb[l][n] lives in lane 8*l+n; owned n = h+2k
    const int sR0 = 8*l + h;
    const int sR1 = sR0 + 2;
    const int sR2 = sR0 + 4;
    const int sR3 = sR0 + 6;

    float* const outLane = out + lane;
    const unsigned msk = 0xffffffffu;

    const int nduo = J >> 1;
    const float2* __restrict__ dist2 = (const float2*)dist;
    const float2* __restrict__ dirs2 = (const float2*)dirs;
    const int2*   __restrict__ ii2p  = (const int2*)idx_i;
    const int2*   __restrict__ jj2p  = (const int2*)idx_j;

    for (int d = warp; d < nduo; d += nwarp) {
        // ---- 2-edge duo loads: 6 LDGs ----
        const float2 r2 = __ldg(dist2 + d);
        const float2 da = __ldg(dirs2 + 3*d + 0);   // x0 y0
        const float2 db = __ldg(dirs2 + 3*d + 1);   // z0 x1
        const float2 dc = __ldg(dirs2 + 3*d + 2);   // y1 z1
        const int2   i2 = __ldg(ii2p + d);
        const int2   j2 = __ldg(jj2p + d);
        const int za = __ldg(zspec + j2.x);
        const int zb = __ldg(zspec + j2.y);

        float* const p0 = outLane + (size_t)(unsigned)(((i2.x << 2) + za) << 7);
        float* const p1 = outLane + (size_t)(unsigned)(((i2.y << 2) + zb) << 7);

        const u64 Rp = pk2(r2.x, r2.y);
        const u64 Xp = pk2(da.x, db.y);
        const u64 Yp = pk2(da.y, dc.x);
        const u64 Zp = pk2(db.x, dc.y);

        // ---- rb front-end, packed: arg = K2E * (r - cen)^2 ----
        u64 T = add2(Rp, NEGCEN);
        T = mul2(T, T);
        T = mul2(T, KK);
        float a0, a1;  upk2(a0, a1, T);
        const float rb0 = ex2(a0);       // rb[k=lane], edge 0 (fc folded in Y)
        const float rb1 = ex2(a1);       // rb[k=lane], edge 1

        // ---- cutoff (scalar; fc folded into Y once) ----
        const float fc0 = cutoff(r2.x);
        const float fc1 = cutoff(r2.y);

        // ---- Y = f1 * (C0 + C1*(P*Q) + C2*z2), packed over the duo ----
        const u64 P  = p_y ? Yp : (p_z ? Zp : Xp);
        const u64 Q  = q_y ? Yp : (q_z ? Zp : Xp);
        const u64 U1 = mul2(P, Q);
        const u64 U2 = mul2(Zp, Zp);
        const u64 f2 = fma2(C1, U1, fma2(C2, U2, C0));
        const u64 F1 = f_y ? Yp : (f_z ? Zp : Xp);
        const u64 Yb = f_one ? f2 : mul2(F1, f2);
        const u64 Ypk = mul2(Yb, pk2(fc0, fc1));
        float y0, y1;  upk2(y0, y1, Ypk);

        // ---- gather rb (4 per edge), scatter 4 REDs per edge ----
        const float A0 = __shfl_sync(msk, rb0, sR0);
        const float A1 = __shfl_sync(msk, rb0, sR1);
        const float A2 = __shfl_sync(msk, rb0, sR2);
        const float A3 = __shfl_sync(msk, rb0, sR3);
        const float B0 = __shfl_sync(msk, rb1, sR0);
        const float B1 = __shfl_sync(msk, rb1, sR1);
        const float B2 = __shfl_sync(msk, rb1, sR2);
        const float B3 = __shfl_sync(msk, rb1, sR3);

        red_f32(p0,      y0 * A0);
        red_f32(p0 + 32, y0 * A1);
        red_f32(p0 + 64, y0 * A2);
        red_f32(p0 + 96, y0 * A3);
        red_f32(p1,      y1 * B0);
        red_f32(p1 + 32, y1 * B1);
        red_f32(p1 + 64, y1 * B2);
        red_f32(p1 + 96, y1 * B3);
    }

    // tail (J odd) — cold scalar path
    for (int e = (nduo << 1) + warp; e < J; e += nwarp) {
        const float r  = __ldg(dist + e);
        const float x  = __ldg(dirs + 3*e + 0);
        const float y  = __ldg(dirs + 3*e + 1);
        const float zz = __ldg(dirs + 3*e + 2);
        const int   ii = __ldg(idx_i + e);
        const int   zj = __ldg(zspec + __ldg(idx_j + e));

        const float fc = cutoff(r);
        const float t  = r - cenf;
        const float rb = ex2(K2E * t * t);

        const float Pv = p_y ? y : (p_z ? zz : x);
        const float Qv = q_y ? y : (q_z ? zz : x);
        const float f2s = cC[lm][0] + cC[lm][1]*Pv*Qv + cC[lm][2]*zz*zz;
        const float F1s = f_y ? y : (f_z ? zz : x);
        const float Y  = (f_one ? f2s : F1s * f2s) * fc;

        const float R0 = __shfl_sync(msk, rb, sR0);
        const float R1 = __shfl_sync(msk, rb, sR1);
        const float R2 = __shfl_sync(msk, rb, sR2);
        const float R3 = __shfl_sync(msk, rb, sR3);

        float* p = outLane + (size_t)(unsigned)(((ii << 2) + zj) << 7);
        red_f32(p,      Y * R0);
        red_f32(p + 32, Y * R1);
        red_f32(p + 64, Y * R2);
        red_f32(p + 96, Y * R3);
    }
}

extern "C" void kernel_launch(void* const* d_in, const int* in_sizes, int n_in,
                              void* d_out, int out_size) {
    const float* dist    = (const float*)d_in[0];
    const float* dirs    = (const float*)d_in[1];
    const float* centers = (const float*)d_in[2];
    const int*   zspec   = (const int*)d_in[3];
    const int*   idx_i   = (const int*)d_in[4];
    const int*   idx_j   = (const int*)d_in[5];
    float*       out     = (float*)d_out;
    const int J = in_sizes[0];

    const int n4 = out_size / 4;
    zero_out_kernel<<<1184, 256>>>((float4*)d_out, n4);

    // Grid = exactly one resident wave: nSM * (blocks/SM at actual reg count).
    int nsm = 148, occ = 4;
    cudaDeviceGetAttribute(&nsm, cudaDevAttrMultiProcessorCount, 0);
    cudaOccupancyMaxActiveBlocksPerMultiprocessor(&occ, sph_expand_kernel, 256, 0);
    if (occ < 1) occ = 1;
    sph_expand_kernel<<<nsm * occ, 256>>>(dist, dirs, centers, zspec,
                                          idx_i, idx_j, out, J);
}

// round 11
// speedup vs baseline: 1.0561x; 1.0561x over previous
#include <cuda_runtime.h>
#include <cstdint>

// ---------------------------------------------------------------------------
// SphericalExpansion, round 11 = R9 4-edge packs (best issue rate)
//                              + R10 compact-Y (best register count).
//
// Strided ownership: lane L owns segment floats {L, L+32, L+64, L+96};
// all share lm = L&15 (lane's own Y); n = (L>>4)+2k -> 4 rb via shfl.idx;
// 4 scalar REDs per edge (one 128B wavefront each).
//
// Y = f1 * (C0 + C1*(P*Q) + C2*z^2), f1/P/Q in {1,x,y,z} via predicates
// (y^2 eliminated with x^2+y^2+z^2=1). Packed coeffs: 3 u64 only.
// 4-edge packs: float4/int4 loads (10 LDGs), 2 packed duos per iteration.
// Launch: occupancy-query adaptive grid (no forced reg cap -> no spills).
// ---------------------------------------------------------------------------

typedef unsigned long long u64;

// f1 selector: 0 = 1, 1 = x, 2 = y, 3 = z
__constant__ int cFS[16] = {0,2,3,1, 0,0,0,0, 0,2,1,2, 3,1,3,1};
// P,Q selectors for U1 = P*Q: 0 = x, 1 = y, 2 = z
__constant__ int cPQ[16][2] = {
    {0,0},{0,0},{0,0},{0,0},
    {0,1},{1,2},{0,0},{2,0},
    {0,0},{0,0},{1,2},{0,0},
    {0,0},{0,0},{0,0},{0,0},
};
// {C0, C1, C2}: Y = f1 * (C0 + C1*(P*Q) + C2*z2)
__constant__ float cC[16][3] = {
    { 0.28209479177387814f, 0.f,                 0.f},
    { 0.4886025119029199f,  0.f,                 0.f},
    { 0.4886025119029199f,  0.f,                 0.f},
    { 0.4886025119029199f,  0.f,                 0.f},
    { 0.f,                  1.0925484305920792f, 0.f},
    { 0.f,                  1.0925484305920792f, 0.f},
    {-0.31539156525252005f, 0.f,                 0.9461746957575602f},
    { 0.f,                  1.0925484305920792f, 0.f},
    {-0.5462742152960396f,  1.0925484305920792f, 0.5462742152960396f},
    {-0.5900435899266435f,  2.360174359706574f,  0.5900435899266435f},
    { 0.f,                  2.890611442640554f,  0.f},
    {-0.4570457994644658f,  0.f,                 2.285228997322329f},
    {-1.1195289977703462f,  0.f,                 1.865881662950577f},
    {-0.4570457994644658f,  0.f,                 2.285228997322329f},
    {-1.445305721320277f,   2.890611442640554f,  1.445305721320277f},
    {-1.7701307697799304f,  2.360174359706574f,  1.7701307697799304f},
};
__constant__ int cLM2L[16] = {0,1,1,1, 2,2,2,2, 2,3,3,3, 3,3,3,3};

#define K2E (-2.8853900817779268f)   // -2*log2(e)

// ---- packed f32x2 helpers ----
__device__ __forceinline__ u64 pk2(float lo, float hi) {
    u64 r; asm("mov.b64 %0, {%1, %2};" : "=l"(r) : "f"(lo), "f"(hi)); return r;
}
__device__ __forceinline__ void upk2(float& lo, float& hi, u64 v) {
    asm("mov.b64 {%0, %1}, %2;" : "=f"(lo), "=f"(hi) : "l"(v));
}
__device__ __forceinline__ u64 mul2(u64 a, u64 b) {
    u64 r; asm("mul.rn.f32x2 %0, %1, %2;" : "=l"(r) : "l"(a), "l"(b)); return r;
}
__device__ __forceinline__ u64 add2(u64 a, u64 b) {
    u64 r; asm("add.rn.f32x2 %0, %1, %2;" : "=l"(r) : "l"(a), "l"(b)); return r;
}
__device__ __forceinline__ u64 fma2(u64 a, u64 b, u64 c) {
    u64 r; asm("fma.rn.f32x2 %0, %1, %2, %3;" : "=l"(r) : "l"(a), "l"(b), "l"(c)); return r;
}
__device__ __forceinline__ float ex2(float a) {
    float r; asm("ex2.approx.f32 %0, %1;" : "=f"(r) : "f"(a)); return r;
}
__device__ __forceinline__ float cutoff(float r) {
    const float u = __saturatef(fmaf(r, 2.0f, -9.0f));
    return fmaf(cospif(u), 0.5f, 0.5f);
}
__device__ __forceinline__ void red_f32(float* p, float v) {
    asm volatile("red.global.add.f32 [%0], %1;" :: "l"(p), "f"(v) : "memory");
}

__global__ void __launch_bounds__(256) zero_out_kernel(float4* out, int n4) {
    int i = blockIdx.x * blockDim.x + threadIdx.x;
    int stride = gridDim.x * blockDim.x;
    float4 zv = make_float4(0.f, 0.f, 0.f, 0.f);
    for (; i < n4; i += stride) out[i] = zv;
}

__global__ void __launch_bounds__(256) sph_expand_kernel(
    const float* __restrict__ dist,
    const float* __restrict__ dirs,      // [J,3]
    const float* __restrict__ centers,   // [32]
    const int*   __restrict__ zspec,     // [N_ATOMS]
    const int*   __restrict__ idx_i,     // [J]
    const int*   __restrict__ idx_j,     // [J]
    float*       __restrict__ out,       // [N_ATOMS*4*8*16]
    int J)
{
    const int lane  = threadIdx.x & 31;
    const int warp  = (blockIdx.x * blockDim.x + threadIdx.x) >> 5;
    const int nwarp = (gridDim.x * blockDim.x) >> 5;

    const int lm = lane & 15;
    const int h  = lane >> 4;            // parity of owned n
    const int l  = cLM2L[lm];

    // per-lane constants (compact: 3 packed coeffs)
    const float cenf = centers[lane];
    const u64 NEGCEN = pk2(-cenf, -cenf);
    const u64 KK = pk2(K2E, K2E);
    const u64 C0 = pk2(cC[lm][0], cC[lm][0]);
    const u64 C1 = pk2(cC[lm][1], cC[lm][1]);
    const u64 C2 = pk2(cC[lm][2], cC[lm][2]);

    // selector predicates (predicate regs, not GPRs)
    const int fs = cFS[lm];
    const int pi = cPQ[lm][0], qi = cPQ[lm][1];
    const bool f_y = (fs == 2), f_z = (fs == 3), f_one = (fs == 0);
    const bool p_y = (pi == 1), p_z = (pi == 2);
    const bool q_y = (qi == 1), q_z = (qi == 2);

    // rb shuffle sources: rb[l][n] lives in lane 8*l+n; owned n = h+2k
    const int sR0 = 8*l + h;
    const int sR1 = sR0 + 2;
    const int sR2 = sR0 + 4;
    const int sR3 = sR0 + 6;

    float* const outLane = out + lane;
    const unsigned msk = 0xffffffffu;

    const int npacks = J >> 2;
    const float4* __restrict__ dist4 = (const float4*)dist;
    const float4* __restrict__ dirs4 = (const float4*)dirs;
    const int4*   __restrict__ ii4p  = (const int4*)idx_i;
    const int4*   __restrict__ jj4p  = (const int4*)idx_j;

    for (int pk = warp; pk < npacks; pk += nwarp) {
        // ---- batch loads: 4 edges, 10 LDGs ----
        const float4 r4 = __ldg(dist4 + pk);
        const float4 d0 = __ldg(dirs4 + 3*pk + 0);
        const float4 d1 = __ldg(dirs4 + 3*pk + 1);
        const float4 d2 = __ldg(dirs4 + 3*pk + 2);
        const int4   i4 = __ldg(ii4p + pk);
        const int4   j4 = __ldg(jj4p + pk);

        const int zs0 = __ldg(zspec + j4.x);
        const int zs1 = __ldg(zspec + j4.y);
        const int zs2 = __ldg(zspec + j4.z);
        const int zs3 = __ldg(zspec + j4.w);

        float* const ptr[4] = {
            outLane + (size_t)(unsigned)(((i4.x << 2) + zs0) << 7),
            outLane + (size_t)(unsigned)(((i4.y << 2) + zs1) << 7),
            outLane + (size_t)(unsigned)(((i4.z << 2) + zs2) << 7),
            outLane + (size_t)(unsigned)(((i4.w << 2) + zs3) << 7),
        };

        // duo layouts: (edge0,edge1) and (edge2,edge3)
        const u64 Rp[2] = { pk2(r4.x, r4.y),  pk2(r4.z, r4.w) };
        const u64 Xp[2] = { pk2(d0.x, d0.w),  pk2(d1.z, d2.y) };
        const u64 Yp[2] = { pk2(d0.y, d1.x),  pk2(d1.w, d2.z) };
        const u64 Zp[2] = { pk2(d0.z, d1.y),  pk2(d2.x, d2.w) };
        const float rsc[4] = { r4.x, r4.y, r4.z, r4.w };

        #pragma unroll
        for (int d = 0; d < 2; d++) {
            // ---- rb front-end, packed: arg = K2E*(r-cen)^2 ----
            u64 T = add2(Rp[d], NEGCEN);
            T = mul2(T, T);
            T = mul2(T, KK);
            float a0, a1;  upk2(a0, a1, T);
            const float rb0 = ex2(a0);
            const float rb1 = ex2(a1);

            // ---- cutoff (scalar, folded into Y once) ----
            const float fc0 = cutoff(rsc[2*d + 0]);
            const float fc1 = cutoff(rsc[2*d + 1]);

            // ---- Y = f1 * (C0 + C1*(P*Q) + C2*z2), packed ----
            const u64 P  = p_y ? Yp[d] : (p_z ? Zp[d] : Xp[d]);
            const u64 Q  = q_y ? Yp[d] : (q_z ? Zp[d] : Xp[d]);
            const u64 U1 = mul2(P, Q);
            const u64 U2 = mul2(Zp[d], Zp[d]);
            const u64 f2 = fma2(C1, U1, fma2(C2, U2, C0));
            const u64 F1 = f_y ? Yp[d] : (f_z ? Zp[d] : Xp[d]);
            const u64 Yb = f_one ? f2 : mul2(F1, f2);
            const u64 Ypk = mul2(Yb, pk2(fc0, fc1));
            float y0, y1;  upk2(y0, y1, Ypk);

            // ---- gather rb (4 per edge), scatter 4 REDs per edge ----
            const float A0 = __shfl_sync(msk, rb0, sR0);
            const float A1 = __shfl_sync(msk, rb0, sR1);
            const float A2 = __shfl_sync(msk, rb0, sR2);
            const float A3 = __shfl_sync(msk, rb0, sR3);
            const float B0 = __shfl_sync(msk, rb1, sR0);
            const float B1 = __shfl_sync(msk, rb1, sR1);
            const float B2 = __shfl_sync(msk, rb1, sR2);
            const float B3 = __shfl_sync(msk, rb1, sR3);

            float* p0 = ptr[2*d + 0];
            float* p1 = ptr[2*d + 1];
            red_f32(p0,      y0 * A0);
            red_f32(p0 + 32, y0 * A1);
            red_f32(p0 + 64, y0 * A2);
            red_f32(p0 + 96, y0 * A3);
            red_f32(p1,      y1 * B0);
            red_f32(p1 + 32, y1 * B1);
            red_f32(p1 + 64, y1 * B2);
            red_f32(p1 + 96, y1 * B3);
        }
    }

    // tail (J not a multiple of 4) — cold scalar path
    for (int e = (npacks << 2) + warp; e < J; e += nwarp) {
        const float r  = __ldg(dist + e);
        const float x  = __ldg(dirs + 3*e + 0);
        const float y  = __ldg(dirs + 3*e + 1);
        const float zz = __ldg(dirs + 3*e + 2);
        const int   ii = __ldg(idx_i + e);
        const int   zj = __ldg(zspec + __ldg(idx_j + e));

        const float fc = cutoff(r);
        const float t  = r - cenf;
        const float rb = ex2(K2E * t * t);

        const float Pv = p_y ? y : (p_z ? zz : x);
        const float Qv = q_y ? y : (q_z ? zz : x);
        const float f2s = cC[lm][0] + cC[lm][1]*Pv*Qv + cC[lm][2]*zz*zz;
        const float F1s = f_y ? y : (f_z ? zz : x);
        const float Y  = (f_one ? f2s : F1s * f2s) * fc;

        const float R0 = __shfl_sync(msk, rb, sR0);
        const float R1 = __shfl_sync(msk, rb, sR1);
        const float R2 = __shfl_sync(msk, rb, sR2);
        const float R3 = __shfl_sync(msk, rb, sR3);

        float* p = outLane + (size_t)(unsigned)(((ii << 2) + zj) << 7);
        red_f32(p,      Y * R0);
        red_f32(p + 32, Y * R1);
        red_f32(p + 64, Y * R2);
        red_f32(p + 96, Y * R3);
    }
}

extern "C" void kernel_launch(void* const* d_in, const int* in_sizes, int n_in,
                              void* d_out, int out_size) {
    const float* dist    = (const float*)d_in[0];
    const float* dirs    = (const float*)d_in[1];
    const float* centers = (const float*)d_in[2];
    const int*   zspec   = (const int*)d_in[3];
    const int*   idx_i   = (const int*)d_in[4];
    const int*   idx_j   = (const int*)d_in[5];
    float*       out     = (float*)d_out;
    const int J = in_sizes[0];

    const int n4 = out_size / 4;
    zero_out_kernel<<<1184, 256>>>((float4*)d_out, n4);

    // Grid = one resident wave at the kernel's ACTUAL occupancy.
    int nsm = 148, occ = 4;
    cudaDeviceGetAttribute(&nsm, cudaDevAttrMultiProcessorCount, 0);
    cudaOccupancyMaxActiveBlocksPerMultiprocessor(&occ, sph_expand_kernel, 256, 0);
    if (occ < 1) occ = 1;
    sph_expand_kernel<<<nsm * occ, 256>>>(dist, dirs, centers, zspec,
                                          idx_i, idx_j, out, J);
}